// round 1
// baseline (speedup 1.0000x reference)
#include <cuda_runtime.h>
#include <math.h>

#define NN 50000
#define EE 800000
#define FULLMASK 0xffffffffu

// ---------------- scratch (static device memory; no allocations) ----------------
__device__ int   g_deg[NN];
__device__ int   g_pos[NN];
__device__ int   g_rowptr[NN + 1];
__device__ int   g_col[EE + NN];
__device__ float g_h1[NN * 256];
__device__ float g_x0[NN * 256];
__device__ float g_as[NN * 8];
__device__ float g_ad[NN * 8];
__device__ float g_out1[NN * 256];
__device__ float g_h2[NN * 256];
__device__ float g_xs[NN * 32];
__device__ float g_out2[NN * 256];
__device__ float g_h3[NN * 32];
__device__ float g_as3[NN];
__device__ float g_ad3[NN];
__device__ float g_scale1[256], g_shift1[256], g_scale2[256], g_shift2[256];

// ---------------- packed fp32x2 FMA (Blackwell FFMA2 pipe) ----------------
__device__ __forceinline__ unsigned long long f2u(float2 v) {
    return ((unsigned long long)__float_as_uint(v.y) << 32) | (unsigned long long)__float_as_uint(v.x);
}
__device__ __forceinline__ float2 u2f(unsigned long long u) {
    return make_float2(__uint_as_float((unsigned)u), __uint_as_float((unsigned)(u >> 32)));
}
__device__ __forceinline__ float2 ffma2(float2 a, float2 b, float2 c) {
    unsigned long long ua = f2u(a), ub = f2u(b), uc = f2u(c), ud;
    asm("fma.rn.f32x2 %0, %1, %2, %3;" : "=l"(ud) : "l"(ua), "l"(ub), "l"(uc));
    return u2f(ud);
}

// ---------------- CSR build ----------------
__global__ void init_deg_kernel(int* deg, int n) {
    int i = blockIdx.x * blockDim.x + threadIdx.x;
    if (i < n) deg[i] = 1;  // self-loop
}

__global__ void count_kernel(const int* __restrict__ dst, int e, int* __restrict__ deg) {
    int i = blockIdx.x * blockDim.x + threadIdx.x;
    if (i < e) atomicAdd(&deg[dst[i]], 1);
}

__global__ void scan_kernel(const int* __restrict__ deg, int* __restrict__ rowptr, int n) {
    __shared__ int buf[1024];
    __shared__ int carry;
    int tid = threadIdx.x;
    if (tid == 0) { carry = 0; rowptr[0] = 0; }
    __syncthreads();
    for (int base = 0; base < n; base += 1024) {
        int i = base + tid;
        int v = (i < n) ? deg[i] : 0;
        buf[tid] = v;
        __syncthreads();
        for (int off = 1; off < 1024; off <<= 1) {
            int t = (tid >= off) ? buf[tid - off] : 0;
            __syncthreads();
            buf[tid] += t;
            __syncthreads();
        }
        if (i < n) rowptr[i + 1] = carry + buf[tid];
        __syncthreads();
        if (tid == 0) carry += buf[1023];
        __syncthreads();
    }
}

__global__ void selfscatter_kernel(const int* __restrict__ rowptr, int* __restrict__ col,
                                   int* __restrict__ pos, int n) {
    int i = blockIdx.x * blockDim.x + threadIdx.x;
    if (i < n) {
        int r = rowptr[i];
        col[r] = i;
        pos[i] = r + 1;
    }
}

__global__ void scatter_kernel(const int* __restrict__ src, const int* __restrict__ dst, int e,
                               int* __restrict__ pos, int* __restrict__ col) {
    int i = blockIdx.x * blockDim.x + threadIdx.x;
    if (i < e) {
        int d = dst[i];
        int p = atomicAdd(&pos[d], 1);
        col[p] = src[i];
    }
}

// ---------------- BN fold ----------------
__global__ void bnprep_kernel(const float* b1, const float* g1, const float* be1,
                              const float* m1, const float* v1,
                              const float* b2, const float* g2, const float* be2,
                              const float* m2, const float* v2) {
    int t = threadIdx.x;
    if (t < 256) {
        float s1 = g1[t] * rsqrtf(v1[t] + 1e-5f);
        g_scale1[t] = s1;
        g_shift1[t] = be1[t] + (b1[t] - m1[t]) * s1;
        float s2 = g2[t] * rsqrtf(v2[t] + 1e-5f);
        g_scale2[t] = s2;
        g_shift2[t] = be2[t] + (b2[t] - m2[t]) * s2;
    }
}

// ---------------- SGEMM: C[M,Nc] = A[M,K] @ B[K,Nc] (+bias) ----------------
// 128x128x16 block tile, 256 threads, 8x8 per thread, fp32x2 FMAs.
__global__ void __launch_bounds__(256, 2)
sgemm_kernel(const float* __restrict__ A, int lda,
             const float* __restrict__ B, int ldb,
             float* __restrict__ C, int ldc,
             int M, int Nc, int K,
             const float* __restrict__ bias) {
    __shared__ float As[16][128];
    __shared__ float Bs[16][128];
    const int tid = threadIdx.x;
    const int bm = blockIdx.y * 128;
    const int bn = blockIdx.x * 128;
    const int tx = tid & 15;         // n direction
    const int ty = tid >> 4;         // m direction
    const int arow = tid >> 2;       // 0..63
    const int acol = (tid & 3) << 2; // 0,4,8,12
    const int brow = tid >> 5;       // 0..7
    const int bcol = (tid & 31) << 2;

    float2 acc[8][4];
#pragma unroll
    for (int i = 0; i < 8; i++)
#pragma unroll
        for (int j = 0; j < 4; j++) acc[i][j] = make_float2(0.f, 0.f);

    for (int k0 = 0; k0 < K; k0 += 16) {
#pragma unroll
        for (int rr = 0; rr < 2; ++rr) {
            int r = arow + rr * 64;
            int gr = bm + r;
            float4 v = make_float4(0.f, 0.f, 0.f, 0.f);
            if (gr < M) v = *reinterpret_cast<const float4*>(A + (size_t)gr * lda + k0 + acol);
            As[acol + 0][r] = v.x; As[acol + 1][r] = v.y;
            As[acol + 2][r] = v.z; As[acol + 3][r] = v.w;
        }
#pragma unroll
        for (int rr = 0; rr < 2; ++rr) {
            int r = brow + rr * 8;
            int gc = bn + bcol;
            float4 v = make_float4(0.f, 0.f, 0.f, 0.f);
            const float* bp = B + (size_t)(k0 + r) * ldb;
            if (gc + 3 < Nc) {
                v = *reinterpret_cast<const float4*>(bp + gc);
            } else if (gc < Nc) {
                v.x = bp[gc];
                if (gc + 1 < Nc) v.y = bp[gc + 1];
                if (gc + 2 < Nc) v.z = bp[gc + 2];
            }
            *reinterpret_cast<float4*>(&Bs[r][bcol]) = v;
        }
        __syncthreads();
#pragma unroll
        for (int kk = 0; kk < 16; ++kk) {
            float4 a0 = *reinterpret_cast<const float4*>(&As[kk][ty * 8]);
            float4 a1 = *reinterpret_cast<const float4*>(&As[kk][ty * 8 + 4]);
            float4 b0 = *reinterpret_cast<const float4*>(&Bs[kk][tx * 8]);
            float4 b1 = *reinterpret_cast<const float4*>(&Bs[kk][tx * 8 + 4]);
            float av[8] = {a0.x, a0.y, a0.z, a0.w, a1.x, a1.y, a1.z, a1.w};
            float2 bv[4] = {make_float2(b0.x, b0.y), make_float2(b0.z, b0.w),
                            make_float2(b1.x, b1.y), make_float2(b1.z, b1.w)};
#pragma unroll
            for (int i = 0; i < 8; i++) {
                float2 ap = make_float2(av[i], av[i]);
#pragma unroll
                for (int j = 0; j < 4; j++) acc[i][j] = ffma2(ap, bv[j], acc[i][j]);
            }
        }
        __syncthreads();
    }

#pragma unroll
    for (int i = 0; i < 8; i++) {
        int gr = bm + ty * 8 + i;
        if (gr >= M) continue;
        float* cp = C + (size_t)gr * ldc;
#pragma unroll
        for (int j = 0; j < 4; j++) {
            int gc = bn + tx * 8 + j * 2;
            float2 v = acc[i][j];
            if (bias) {
                if (gc < Nc) v.x += bias[gc];
                if (gc + 1 < Nc) v.y += bias[gc + 1];
            }
            if (gc < Nc) cp[gc] = v.x;
            if (gc + 1 < Nc) cp[gc + 1] = v.y;
        }
    }
}

// ---------------- attention logits: alpha_s/d[n,h] = sum_c h[n,h,c]*a[h,c] ----------------
__global__ void alpha_kernel(const float* __restrict__ h, int ld,
                             const float* __restrict__ asrc, const float* __restrict__ adst,
                             float* __restrict__ s_out, float* __restrict__ d_out_,
                             int n, int heads) {
    int node = (blockIdx.x * blockDim.x + threadIdx.x) >> 5;
    if (node >= n) return;
    int lane = threadIdx.x & 31;
    const float* hr = h + (size_t)node * ld;
#pragma unroll
    for (int hd = 0; hd < 8; ++hd) {
        if (hd >= heads) break;
        float v = hr[hd * 32 + lane];
        float ps = v * asrc[hd * 32 + lane];
        float pd = v * adst[hd * 32 + lane];
#pragma unroll
        for (int off = 16; off; off >>= 1) {
            ps += __shfl_xor_sync(FULLMASK, ps, off);
            pd += __shfl_xor_sync(FULLMASK, pd, off);
        }
        if (lane == 0) {
            s_out[(size_t)node * heads + hd] = ps;
            d_out_[(size_t)node * heads + hd] = pd;
        }
    }
}

// ---------------- 8-head aggregation + BN/ELU/skip epilogue (warp per dst node) ----------------
__global__ void agg8_kernel(const float* __restrict__ h, int hld,
                            const float* __restrict__ as_, const float* __restrict__ ad_,
                            const int* __restrict__ rowptr, const int* __restrict__ col,
                            const float* __restrict__ scale, const float* __restrict__ shift,
                            const float* __restrict__ skip,
                            float* __restrict__ out, int n) {
    int node = (blockIdx.x * blockDim.x + threadIdx.x) >> 5;
    if (node >= n) return;
    int lane = threadIdx.x & 31;
    int hd8 = lane & 7;
    float adv = ad_[(size_t)node * 8 + hd8];
    int start = rowptr[node], end = rowptr[node + 1];
    float acc[8];
#pragma unroll
    for (int i = 0; i < 8; i++) acc[i] = 0.f;
    float denom = 0.f;
    for (int j = start; j < end; ++j) {
        int s = __ldg(&col[j]);
        float asv = __ldg(&as_[(size_t)s * 8 + hd8]);
        float e = asv + adv;
        e = e > 0.f ? e : 0.2f * e;
        float w = __expf(e);
        denom += w;
        const float* hr = h + (size_t)s * hld;
#pragma unroll
        for (int hd = 0; hd < 8; ++hd) {
            float wh = __shfl_sync(FULLMASK, w, hd);
            acc[hd] = fmaf(wh, __ldg(&hr[hd * 32 + lane]), acc[hd]);
        }
    }
#pragma unroll
    for (int hd = 0; hd < 8; ++hd) {
        float dh = __shfl_sync(FULLMASK, denom, hd) + 1e-16f;
        int ch = hd * 32 + lane;
        float y = acc[hd] / dh;
        y = y * scale[ch] + shift[ch];
        y = y > 0.f ? y : expm1f(y);
        if (skip) y += skip[(size_t)node * 256 + ch];
        out[(size_t)node * 256 + ch] = y;
    }
}

// ---------------- 1-head final aggregation + bias + skip ----------------
__global__ void agg1_kernel(const float* __restrict__ h3,
                            const float* __restrict__ as3, const float* __restrict__ ad3,
                            const int* __restrict__ rowptr, const int* __restrict__ col,
                            const float* __restrict__ b3, const float* __restrict__ xs,
                            float* __restrict__ out, int n) {
    int node = (blockIdx.x * blockDim.x + threadIdx.x) >> 5;
    if (node >= n) return;
    int lane = threadIdx.x & 31;
    float adv = ad3[node];
    int start = rowptr[node], end = rowptr[node + 1];
    float acc = 0.f, denom = 0.f;
    for (int j = start; j < end; ++j) {
        int s = __ldg(&col[j]);
        float e = __ldg(&as3[s]) + adv;
        e = e > 0.f ? e : 0.2f * e;
        float w = __expf(e);
        denom += w;
        acc = fmaf(w, __ldg(&h3[(size_t)s * 32 + lane]), acc);
    }
    out[(size_t)node * 32 + lane] = acc / (denom + 1e-16f) + b3[lane] + xs[(size_t)node * 32 + lane];
}

// ---------------- host launcher ----------------
#define GSYM(ptr, sym) do { void* _t; cudaGetSymbolAddress(&_t, sym); ptr = (decltype(ptr))_t; } while (0)

extern "C" void kernel_launch(void* const* d_in, const int* in_sizes, int n_in,
                              void* d_out, int out_size) {
    const float* x      = (const float*)d_in[0];
    const int*   ei     = (const int*)d_in[1];
    const float* W1     = (const float*)d_in[2];
    const float* a_src1 = (const float*)d_in[3];
    const float* a_dst1 = (const float*)d_in[4];
    const float* b1     = (const float*)d_in[5];
    const float* bn1_g  = (const float*)d_in[6];
    const float* bn1_b  = (const float*)d_in[7];
    const float* bn1_m  = (const float*)d_in[8];
    const float* bn1_v  = (const float*)d_in[9];
    const float* W2     = (const float*)d_in[10];
    const float* a_src2 = (const float*)d_in[11];
    const float* a_dst2 = (const float*)d_in[12];
    const float* b2     = (const float*)d_in[13];
    const float* bn2_g  = (const float*)d_in[14];
    const float* bn2_b  = (const float*)d_in[15];
    const float* bn2_m  = (const float*)d_in[16];
    const float* bn2_v  = (const float*)d_in[17];
    const float* W3     = (const float*)d_in[18];
    const float* a_src3 = (const float*)d_in[19];
    const float* a_dst3 = (const float*)d_in[20];
    const float* b3     = (const float*)d_in[21];
    const float* Ws1    = (const float*)d_in[22];
    const float* bs1    = (const float*)d_in[23];
    const float* Ws2    = (const float*)d_in[24];
    const float* bs2    = (const float*)d_in[25];

    const int N = in_sizes[0] / 128;
    const int E = in_sizes[1] / 2;
    const int* srcp = ei;
    const int* dstp = ei + E;

    int *deg, *pos, *rowptr, *col;
    float *h1, *x0, *as_, *ad_, *out1, *h2, *xs, *out2, *h3, *as3, *ad3;
    float *scale1, *shift1, *scale2, *shift2;
    GSYM(deg, g_deg); GSYM(pos, g_pos); GSYM(rowptr, g_rowptr); GSYM(col, g_col);
    GSYM(h1, g_h1); GSYM(x0, g_x0); GSYM(as_, g_as); GSYM(ad_, g_ad);
    GSYM(out1, g_out1); GSYM(h2, g_h2); GSYM(xs, g_xs); GSYM(out2, g_out2);
    GSYM(h3, g_h3); GSYM(as3, g_as3); GSYM(ad3, g_ad3);
    GSYM(scale1, g_scale1); GSYM(shift1, g_shift1);
    GSYM(scale2, g_scale2); GSYM(shift2, g_shift2);

    const int TB = 256;
    const int nb_N  = (N + TB - 1) / TB;
    const int nb_E  = (E + TB - 1) / TB;
    const int nb_W  = (N * 32 + TB - 1) / TB;   // warp-per-node grids
    const int gy    = (N + 127) / 128;

    // CSR build (dst-sorted adjacency incl. self-loops)
    init_deg_kernel<<<nb_N, TB>>>(deg, N);
    count_kernel<<<nb_E, TB>>>(dstp, E, deg);
    scan_kernel<<<1, 1024>>>(deg, rowptr, N);
    selfscatter_kernel<<<nb_N, TB>>>(rowptr, col, pos, N);
    scatter_kernel<<<nb_E, TB>>>(srcp, dstp, E, pos, col);

    bnprep_kernel<<<1, 256>>>(b1, bn1_g, bn1_b, bn1_m, bn1_v,
                              b2, bn2_g, bn2_b, bn2_m, bn2_v);

    // Layer 1
    sgemm_kernel<<<dim3(2, gy), TB>>>(x, 128, W1, 256, h1, 256, N, 256, 128, nullptr);
    sgemm_kernel<<<dim3(2, gy), TB>>>(x, 128, Ws1, 256, x0, 256, N, 256, 128, bs1);
    alpha_kernel<<<nb_W, TB>>>(h1, 256, a_src1, a_dst1, as_, ad_, N, 8);
    agg8_kernel<<<nb_W, TB>>>(h1, 256, as_, ad_, rowptr, col, scale1, shift1, x0, out1, N);

    // Layer 2
    sgemm_kernel<<<dim3(2, gy), TB>>>(out1, 256, W2, 256, h2, 256, N, 256, 256, nullptr);
    sgemm_kernel<<<dim3(1, gy), TB>>>(out1, 256, Ws2, 32, xs, 32, N, 32, 256, bs2);
    alpha_kernel<<<nb_W, TB>>>(h2, 256, a_src2, a_dst2, as_, ad_, N, 8);
    agg8_kernel<<<nb_W, TB>>>(h2, 256, as_, ad_, rowptr, col, scale2, shift2, nullptr, out2, N);

    // Layer 3
    sgemm_kernel<<<dim3(1, gy), TB>>>(out2, 256, W3, 32, h3, 32, N, 32, 256, nullptr);
    alpha_kernel<<<nb_W, TB>>>(h3, 32, a_src3, a_dst3, as3, ad3, N, 1);
    agg1_kernel<<<nb_W, TB>>>(h3, as3, ad3, rowptr, col, b3, xs, (float*)d_out, N);
}

// round 3
// speedup vs baseline: 1.7966x; 1.7966x over previous
#include <cuda_runtime.h>
#include <cuda_bf16.h>
#include <math.h>

#define NN 50000
#define EE 800000
#define FULLMASK 0xffffffffu
#define STR 34   // smem k-stride in bf16 elems (17 words -> conflict-free)

// ---------------- scratch (static device memory; no allocations) ----------------
__device__ int   g_deg[NN];
__device__ int   g_pos[NN];
__device__ int   g_rowptr[NN + 1];
__device__ int   g_col[EE + NN];
__device__ float g_h1[NN * 256];
__device__ float g_x0[NN * 256];
__device__ float g_as[NN * 8];
__device__ float g_ad[NN * 8];
__device__ float g_out1[NN * 256];
__device__ float g_h2[NN * 256];
__device__ float g_xs[NN * 32];
__device__ float g_out2[NN * 256];
__device__ float g_h3[NN * 32];
__device__ float g_as3[NN];
__device__ float g_ad3[NN];
__device__ float g_scale1[256], g_shift1[256], g_scale2[256], g_shift2[256];

// ---------------- CSR build ----------------
__global__ void init_deg_kernel(int* deg, int n) {
    int i = blockIdx.x * blockDim.x + threadIdx.x;
    if (i < n) deg[i] = 1;  // self-loop
}

__global__ void count_kernel(const int* __restrict__ dst, int e, int* __restrict__ deg) {
    int i = blockIdx.x * blockDim.x + threadIdx.x;
    if (i < e) atomicAdd(&deg[dst[i]], 1);
}

// single-block warp-shuffle scan: 1024 threads x 4 elems / iter
__global__ void scan_kernel(const int* __restrict__ deg, int* __restrict__ rowptr, int n) {
    __shared__ int wsum[32];
    __shared__ int s_carry;
    int tid = threadIdx.x, lane = tid & 31, wid = tid >> 5;
    if (tid == 0) { s_carry = 0; rowptr[0] = 0; }
    __syncthreads();
    for (int base = 0; base < n; base += 4096) {
        int i = base + tid * 4;
        int v0 = (i     < n) ? deg[i]     : 0;
        int v1 = (i + 1 < n) ? deg[i + 1] : 0;
        int v2 = (i + 2 < n) ? deg[i + 2] : 0;
        int v3 = (i + 3 < n) ? deg[i + 3] : 0;
        int s = v0 + v1 + v2 + v3;
        int inc = s;
#pragma unroll
        for (int off = 1; off < 32; off <<= 1) {
            int t = __shfl_up_sync(FULLMASK, inc, off);
            if (lane >= off) inc += t;
        }
        if (lane == 31) wsum[wid] = inc;
        __syncthreads();
        if (wid == 0) {
            int w = wsum[lane];
#pragma unroll
            for (int off = 1; off < 32; off <<= 1) {
                int t = __shfl_up_sync(FULLMASK, w, off);
                if (lane >= off) w += t;
            }
            wsum[lane] = w;
        }
        __syncthreads();
        int excl = s_carry + (wid ? wsum[wid - 1] : 0) + (inc - s);
        if (i     < n) rowptr[i + 1] = excl + v0;
        if (i + 1 < n) rowptr[i + 2] = excl + v0 + v1;
        if (i + 2 < n) rowptr[i + 3] = excl + v0 + v1 + v2;
        if (i + 3 < n) rowptr[i + 4] = excl + s;
        __syncthreads();
        if (tid == 0) s_carry += wsum[31];
        __syncthreads();
    }
}

__global__ void selfscatter_kernel(const int* __restrict__ rowptr, int* __restrict__ col,
                                   int* __restrict__ pos, int n) {
    int i = blockIdx.x * blockDim.x + threadIdx.x;
    if (i < n) {
        int r = rowptr[i];
        col[r] = i;
        pos[i] = r + 1;
    }
}

__global__ void scatter_kernel(const int* __restrict__ src, const int* __restrict__ dst, int e,
                               int* __restrict__ pos, int* __restrict__ col) {
    int i = blockIdx.x * blockDim.x + threadIdx.x;
    if (i < e) {
        int d = dst[i];
        int p = atomicAdd(&pos[d], 1);
        col[p] = src[i];
    }
}

// ---------------- BN fold ----------------
__global__ void bnprep_kernel(const float* b1, const float* g1, const float* be1,
                              const float* m1, const float* v1,
                              const float* b2, const float* g2, const float* be2,
                              const float* m2, const float* v2) {
    int t = threadIdx.x;
    if (t < 256) {
        float s1 = g1[t] * rsqrtf(v1[t] + 1e-5f);
        g_scale1[t] = s1;
        g_shift1[t] = be1[t] + (b1[t] - m1[t]) * s1;
        float s2 = g2[t] * rsqrtf(v2[t] + 1e-5f);
        g_scale2[t] = s2;
        g_shift2[t] = be2[t] + (b2[t] - m2[t]) * s2;
    }
}

// ---------------- tensor-core GEMM (bf16 split-3, m16n8k16 HMMA) ----------------
__device__ __forceinline__ void mma_bf16(float* c, const unsigned* a, unsigned b0, unsigned b1) {
    asm volatile(
        "mma.sync.aligned.m16n8k16.row.col.f32.bf16.bf16.f32 "
        "{%0,%1,%2,%3}, {%4,%5,%6,%7}, {%8,%9}, {%0,%1,%2,%3};"
        : "+f"(c[0]), "+f"(c[1]), "+f"(c[2]), "+f"(c[3])
        : "r"(a[0]), "r"(a[1]), "r"(a[2]), "r"(a[3]), "r"(b0), "r"(b1));
}

// C[M, NcT] = A[M,K] @ [B1 | B2]  with epilogue routing: cols < split -> C1,
// cols >= split -> C2 (+bias2). Block tile 128x128, KT=32, 256 threads.
__global__ void __launch_bounds__(256)
mma_gemm_kernel(const float* __restrict__ A, int lda, int M, int K,
                const float* __restrict__ B1, int ldb1,
                const float* __restrict__ B2, int ldb2, int w2,
                int split, int NcT,
                float* __restrict__ C1, int ldc1,
                float* __restrict__ C2, int ldc2,
                const float* __restrict__ bias2) {
    __shared__ __align__(16) __nv_bfloat16 sAhi[128 * STR];
    __shared__ __align__(16) __nv_bfloat16 sAlo[128 * STR];
    __shared__ __align__(16) __nv_bfloat16 sBhi[128 * STR];
    __shared__ __align__(16) __nv_bfloat16 sBlo[128 * STR];

    const int tid  = threadIdx.x;
    const int lane = tid & 31, warp = tid >> 5;
    const int wm = (warp & 3) * 32;    // warp m-offset (4 warps in m)
    const int wn = (warp >> 2) * 64;   // warp n-offset (2 warps in n)
    const int g  = lane >> 2, t2 = (lane & 3) * 2;
    const int bm = blockIdx.y * 128, bn = blockIdx.x * 128;

    // staging maps
    const int ar = tid >> 1, ak = (tid & 1) * 16;   // A: row ar, 16 cols from ak
    const int bnn = tid & 127, bk = (tid >> 7) * 16; // B: col bnn, 16 k's from bk
    const bool a_ok = (bm + ar) < M;

    const int gcol = bn + bnn;
    const float* bsrc = nullptr;
    int bld = 0;
    if (gcol < split)               { bsrc = B1 + gcol;          bld = ldb1; }
    else if (gcol - split < w2)     { bsrc = B2 + (gcol - split); bld = ldb2; }

    float acc[2][8][4];
#pragma unroll
    for (int mf = 0; mf < 2; mf++)
#pragma unroll
        for (int nf = 0; nf < 8; nf++)
#pragma unroll
            for (int q = 0; q < 4; q++) acc[mf][nf][q] = 0.f;

    float regA[16], regB[16];

    // prefetch k0 = 0
    {
        const float* ap = A + (size_t)(bm + ar) * lda + ak;
#pragma unroll
        for (int v = 0; v < 4; v++) {
            float4 t = a_ok ? *reinterpret_cast<const float4*>(ap + v * 4)
                            : make_float4(0.f, 0.f, 0.f, 0.f);
            regA[v * 4 + 0] = t.x; regA[v * 4 + 1] = t.y;
            regA[v * 4 + 2] = t.z; regA[v * 4 + 3] = t.w;
        }
#pragma unroll
        for (int j = 0; j < 16; j++)
            regB[j] = bsrc ? bsrc[(size_t)(bk + j) * bld] : 0.f;
    }

    for (int k0 = 0; k0 < K; k0 += 32) {
        __syncthreads();
        // store staged tile (fp32 -> hi/lo bf16 split)
#pragma unroll
        for (int j = 0; j < 16; j++) {
            float f = regA[j];
            __nv_bfloat16 h = __float2bfloat16(f);
            sAhi[ar * STR + ak + j] = h;
            sAlo[ar * STR + ak + j] = __float2bfloat16(f - __bfloat162float(h));
        }
#pragma unroll
        for (int j = 0; j < 16; j++) {
            float f = regB[j];
            __nv_bfloat16 h = __float2bfloat16(f);
            sBhi[bnn * STR + bk + j] = h;
            sBlo[bnn * STR + bk + j] = __float2bfloat16(f - __bfloat162float(h));
        }
        __syncthreads();

        if (k0 + 32 < K) {  // prefetch next tile (overlaps with MMA below)
            const float* ap = A + (size_t)(bm + ar) * lda + (k0 + 32 + ak);
#pragma unroll
            for (int v = 0; v < 4; v++) {
                float4 t = a_ok ? *reinterpret_cast<const float4*>(ap + v * 4)
                                : make_float4(0.f, 0.f, 0.f, 0.f);
                regA[v * 4 + 0] = t.x; regA[v * 4 + 1] = t.y;
                regA[v * 4 + 2] = t.z; regA[v * 4 + 3] = t.w;
            }
#pragma unroll
            for (int j = 0; j < 16; j++)
                regB[j] = bsrc ? bsrc[(size_t)(k0 + 32 + bk + j) * bld] : 0.f;
        }

        // two k16 MMA steps
#pragma unroll
        for (int ks = 0; ks < 2; ks++) {
            const int ko = ks * 16;
            unsigned ah[2][4], al[2][4];
#pragma unroll
            for (int mf = 0; mf < 2; mf++) {
                int r0 = (wm + mf * 16 + g) * STR + ko + t2;
                int r1 = r0 + 8 * STR;
                ah[mf][0] = *reinterpret_cast<const unsigned*>(&sAhi[r0]);
                ah[mf][1] = *reinterpret_cast<const unsigned*>(&sAhi[r1]);
                ah[mf][2] = *reinterpret_cast<const unsigned*>(&sAhi[r0 + 8]);
                ah[mf][3] = *reinterpret_cast<const unsigned*>(&sAhi[r1 + 8]);
                al[mf][0] = *reinterpret_cast<const unsigned*>(&sAlo[r0]);
                al[mf][1] = *reinterpret_cast<const unsigned*>(&sAlo[r1]);
                al[mf][2] = *reinterpret_cast<const unsigned*>(&sAlo[r0 + 8]);
                al[mf][3] = *reinterpret_cast<const unsigned*>(&sAlo[r1 + 8]);
            }
#pragma unroll
            for (int nf = 0; nf < 8; nf++) {
                int c0 = (wn + nf * 8 + g) * STR + ko + t2;
                unsigned bh0 = *reinterpret_cast<const unsigned*>(&sBhi[c0]);
                unsigned bh1 = *reinterpret_cast<const unsigned*>(&sBhi[c0 + 8]);
                unsigned bl0 = *reinterpret_cast<const unsigned*>(&sBlo[c0]);
                unsigned bl1 = *reinterpret_cast<const unsigned*>(&sBlo[c0 + 8]);
#pragma unroll
                for (int mf = 0; mf < 2; mf++) {
                    mma_bf16(acc[mf][nf], ah[mf], bh0, bh1);
                    mma_bf16(acc[mf][nf], al[mf], bh0, bh1);
                    mma_bf16(acc[mf][nf], ah[mf], bl0, bl1);
                }
            }
        }
    }

    // epilogue with routing
#pragma unroll
    for (int mf = 0; mf < 2; mf++) {
#pragma unroll
        for (int half = 0; half < 2; half++) {
            int rr = bm + wm + mf * 16 + g + half * 8;
            if (rr >= M) continue;
#pragma unroll
            for (int nf = 0; nf < 8; nf++) {
#pragma unroll
                for (int q = 0; q < 2; q++) {
                    int cc = bn + wn + nf * 8 + t2 + q;
                    if (cc >= NcT) continue;
                    float v = acc[mf][nf][half * 2 + q];
                    if (cc < split) {
                        C1[(size_t)rr * ldc1 + cc] = v;
                    } else {
                        int c2 = cc - split;
                        if (bias2) v += bias2[c2];
                        C2[(size_t)rr * ldc2 + c2] = v;
                    }
                }
            }
        }
    }
}

// ---------------- attention logits ----------------
__global__ void alpha_kernel(const float* __restrict__ h, int ld,
                             const float* __restrict__ asrc, const float* __restrict__ adst,
                             float* __restrict__ s_out, float* __restrict__ d_out_,
                             int n, int heads) {
    int node = (blockIdx.x * blockDim.x + threadIdx.x) >> 5;
    if (node >= n) return;
    int lane = threadIdx.x & 31;
    const float* hr = h + (size_t)node * ld;
#pragma unroll
    for (int hd = 0; hd < 8; ++hd) {
        if (hd >= heads) break;
        float v = hr[hd * 32 + lane];
        float ps = v * asrc[hd * 32 + lane];
        float pd = v * adst[hd * 32 + lane];
#pragma unroll
        for (int off = 16; off; off >>= 1) {
            ps += __shfl_xor_sync(FULLMASK, ps, off);
            pd += __shfl_xor_sync(FULLMASK, pd, off);
        }
        if (lane == 0) {
            s_out[(size_t)node * heads + hd] = ps;
            d_out_[(size_t)node * heads + hd] = pd;
        }
    }
}

// ---------------- 8-head aggregation + BN/ELU/skip epilogue ----------------
__global__ void agg8_kernel(const float* __restrict__ h, int hld,
                            const float* __restrict__ as_, const float* __restrict__ ad_,
                            const int* __restrict__ rowptr, const int* __restrict__ col,
                            const float* __restrict__ scale, const float* __restrict__ shift,
                            const float* __restrict__ skip,
                            float* __restrict__ out, int n) {
    int node = (blockIdx.x * blockDim.x + threadIdx.x) >> 5;
    if (node >= n) return;
    int lane = threadIdx.x & 31;
    int hd8 = lane & 7;
    float adv = ad_[(size_t)node * 8 + hd8];
    int start = rowptr[node], end = rowptr[node + 1];
    float acc[8];
#pragma unroll
    for (int i = 0; i < 8; i++) acc[i] = 0.f;
    float denom = 0.f;
    for (int j = start; j < end; ++j) {
        int s = __ldg(&col[j]);
        float asv = __ldg(&as_[(size_t)s * 8 + hd8]);
        float e = asv + adv;
        e = e > 0.f ? e : 0.2f * e;
        float w = __expf(e);
        denom += w;
        const float* hr = h + (size_t)s * hld;
#pragma unroll
        for (int hd = 0; hd < 8; ++hd) {
            float wh = __shfl_sync(FULLMASK, w, hd);
            acc[hd] = fmaf(wh, __ldg(&hr[hd * 32 + lane]), acc[hd]);
        }
    }
#pragma unroll
    for (int hd = 0; hd < 8; ++hd) {
        float dh = __shfl_sync(FULLMASK, denom, hd) + 1e-16f;
        int ch = hd * 32 + lane;
        float y = acc[hd] / dh;
        y = y * scale[ch] + shift[ch];
        y = y > 0.f ? y : expm1f(y);
        if (skip) y += skip[(size_t)node * 256 + ch];
        out[(size_t)node * 256 + ch] = y;
    }
}

// ---------------- 1-head final aggregation + bias + skip ----------------
__global__ void agg1_kernel(const float* __restrict__ h3,
                            const float* __restrict__ as3, const float* __restrict__ ad3,
                            const int* __restrict__ rowptr, const int* __restrict__ col,
                            const float* __restrict__ b3, const float* __restrict__ xs,
                            float* __restrict__ out, int n) {
    int node = (blockIdx.x * blockDim.x + threadIdx.x) >> 5;
    if (node >= n) return;
    int lane = threadIdx.x & 31;
    float adv = ad3[node];
    int start = rowptr[node], end = rowptr[node + 1];
    float acc = 0.f, denom = 0.f;
    for (int j = start; j < end; ++j) {
        int s = __ldg(&col[j]);
        float e = __ldg(&as3[s]) + adv;
        e = e > 0.f ? e : 0.2f * e;
        float w = __expf(e);
        denom += w;
        acc = fmaf(w, __ldg(&h3[(size_t)s * 32 + lane]), acc);
    }
    out[(size_t)node * 32 + lane] = acc / (denom + 1e-16f) + b3[lane] + xs[(size_t)node * 32 + lane];
}

// ---------------- host launcher ----------------
#define GSYM(ptr, sym) do { void* _t; cudaGetSymbolAddress(&_t, sym); ptr = (decltype(ptr))_t; } while (0)

extern "C" void kernel_launch(void* const* d_in, const int* in_sizes, int n_in,
                              void* d_out, int out_size) {
    const float* x      = (const float*)d_in[0];
    const int*   ei     = (const int*)d_in[1];
    const float* W1     = (const float*)d_in[2];
    const float* a_src1 = (const float*)d_in[3];
    const float* a_dst1 = (const float*)d_in[4];
    const float* b1     = (const float*)d_in[5];
    const float* bn1_g  = (const float*)d_in[6];
    const float* bn1_b  = (const float*)d_in[7];
    const float* bn1_m  = (const float*)d_in[8];
    const float* bn1_v  = (const float*)d_in[9];
    const float* W2     = (const float*)d_in[10];
    const float* a_src2 = (const float*)d_in[11];
    const float* a_dst2 = (const float*)d_in[12];
    const float* b2     = (const float*)d_in[13];
    const float* bn2_g  = (const float*)d_in[14];
    const float* bn2_b  = (const float*)d_in[15];
    const float* bn2_m  = (const float*)d_in[16];
    const float* bn2_v  = (const float*)d_in[17];
    const float* W3     = (const float*)d_in[18];
    const float* a_src3 = (const float*)d_in[19];
    const float* a_dst3 = (const float*)d_in[20];
    const float* b3     = (const float*)d_in[21];
    const float* Ws1    = (const float*)d_in[22];
    const float* bs1    = (const float*)d_in[23];
    const float* Ws2    = (const float*)d_in[24];
    const float* bs2    = (const float*)d_in[25];

    const int N = in_sizes[0] / 128;
    const int E = in_sizes[1] / 2;
    const int* srcp = ei;
    const int* dstp = ei + E;

    int *deg, *pos, *rowptr, *col;
    float *h1, *x0, *as_, *ad_, *out1, *h2, *xs, *out2, *h3, *as3, *ad3;
    float *scale1, *shift1, *scale2, *shift2;
    GSYM(deg, g_deg); GSYM(pos, g_pos); GSYM(rowptr, g_rowptr); GSYM(col, g_col);
    GSYM(h1, g_h1); GSYM(x0, g_x0); GSYM(as_, g_as); GSYM(ad_, g_ad);
    GSYM(out1, g_out1); GSYM(h2, g_h2); GSYM(xs, g_xs); GSYM(out2, g_out2);
    GSYM(h3, g_h3); GSYM(as3, g_as3); GSYM(ad3, g_ad3);
    GSYM(scale1, g_scale1); GSYM(shift1, g_shift1);
    GSYM(scale2, g_scale2); GSYM(shift2, g_shift2);

    const int TB = 256;
    const int nb_N  = (N + TB - 1) / TB;
    const int nb_E  = (E + TB - 1) / TB;
    const int nb_W  = (N * 32 + TB - 1) / TB;   // warp-per-node grids
    const int gy    = (N + 127) / 128;

    // 1-3: CSR prefix
    init_deg_kernel<<<nb_N, TB>>>(deg, N);
    count_kernel<<<nb_E, TB>>>(dstp, E, deg);
    scan_kernel<<<1, 1024>>>(deg, rowptr, N);

    // 4: layer-1 fused GEMM  (h1 = x@W1 ; x0 = x@Ws1 + bs1)
    mma_gemm_kernel<<<dim3(4, gy), TB>>>(x, 128, N, 128,
                                         W1, 256, Ws1, 256, 256,
                                         256, 512,
                                         h1, 256, x0, 256, bs1);

    // 5-7: finish CSR + BN fold
    selfscatter_kernel<<<nb_N, TB>>>(rowptr, col, pos, N);
    scatter_kernel<<<nb_E, TB>>>(srcp, dstp, E, pos, col);
    bnprep_kernel<<<1, 256>>>(b1, bn1_g, bn1_b, bn1_m, bn1_v,
                              b2, bn2_g, bn2_b, bn2_m, bn2_v);

    // 8-9: layer-1 attention + aggregation
    alpha_kernel<<<nb_W, TB>>>(h1, 256, a_src1, a_dst1, as_, ad_, N, 8);
    agg8_kernel<<<nb_W, TB>>>(h1, 256, as_, ad_, rowptr, col, scale1, shift1, x0, out1, N);

    // 10-12: layer 2  (h2 = out1@W2 ; xs = out1@Ws2 + bs2)
    mma_gemm_kernel<<<dim3(3, gy), TB>>>(out1, 256, N, 256,
                                         W2, 256, Ws2, 32, 32,
                                         256, 288,
                                         h2, 256, xs, 32, bs2);
    alpha_kernel<<<nb_W, TB>>>(h2, 256, a_src2, a_dst2, as_, ad_, N, 8);
    agg8_kernel<<<nb_W, TB>>>(h2, 256, as_, ad_, rowptr, col, scale2, shift2, nullptr, out2, N);

    // 13-15: layer 3
    mma_gemm_kernel<<<dim3(1, gy), TB>>>(out2, 256, N, 256,
                                         W3, 32, W3, 32, 0,
                                         32, 32,
                                         h3, 32, h3, 32, nullptr);
    alpha_kernel<<<nb_W, TB>>>(h3, 32, a_src3, a_dst3, as3, ad3, N, 1);
    agg1_kernel<<<nb_W, TB>>>(h3, as3, ad3, rowptr, col, b3, xs, (float*)d_out, N);
}